// round 4
// baseline (speedup 1.0000x reference)
#include <cuda_runtime.h>
#include <cstdint>

#define BB 64      // batch
#define TT 1024    // time steps
#define EE 512     // embedding
#define VV 256     // vocab

typedef unsigned long long ull;

// ---------------- device scratch ----------------
__device__ float g_xwv[VV * EE];                 // XWV[v][o] = emb[v]·w_x[o] + b_cell[o]
__device__ float g_hs[(size_t)BB * TT * EE];     // h_t, layout [b][t][e]  (128 MB)
__device__ unsigned int g_bar[4 * 32];           // per-group counter, 128B apart

// ---------------- f32x2 helpers ----------------
__device__ __forceinline__ ull ffma2(ull a, ull b, ull c) {
    ull d;
    asm("fma.rn.f32x2 %0, %1, %2, %3;" : "=l"(d) : "l"(a), "l"(b), "l"(c));
    return d;
}
__device__ __forceinline__ ull fdup(float s) {
    ull d;
    asm("mov.b64 %0, {%1, %1};" : "=l"(d) : "f"(s));
    return d;
}
__device__ __forceinline__ float2 unpack2(ull v) {
    float2 r;
    asm("mov.b64 {%0, %1}, %2;" : "=f"(r.x), "=f"(r.y) : "l"(v));
    return r;
}

// =====================================================================
// Small GEMM for phase 1:  C[M][N] = A[M][K] @ B[N][K]^T + bias[N]
// grid = (M/64, N/64), block = 256, 4x4 microtile (fp32)
// =====================================================================
__global__ void gemm_atb(const float* __restrict__ A, int lda,
                         const float* __restrict__ Bm, int ldb,
                         const float* __restrict__ bias,
                         float* __restrict__ C, int N, int K)
{
    __shared__ float As[16][64];
    __shared__ float Bs[16][64];

    const int tid  = threadIdx.x;
    const int m0   = blockIdx.x * 64;
    const int n0   = blockIdx.y * 64;
    const int tx   = tid & 15;
    const int ty   = tid >> 4;
    const int lrow = tid >> 2;
    const int lcol = (tid & 3) * 4;

    float acc[4][4];
#pragma unroll
    for (int i = 0; i < 4; ++i)
#pragma unroll
        for (int j = 0; j < 4; ++j) acc[i][j] = 0.0f;

    for (int k0 = 0; k0 < K; k0 += 16) {
        float4 av = *reinterpret_cast<const float4*>(A  + (size_t)(m0 + lrow) * lda + k0 + lcol);
        float4 bv = *reinterpret_cast<const float4*>(Bm + (size_t)(n0 + lrow) * ldb + k0 + lcol);
        As[lcol + 0][lrow] = av.x;  As[lcol + 1][lrow] = av.y;
        As[lcol + 2][lrow] = av.z;  As[lcol + 3][lrow] = av.w;
        Bs[lcol + 0][lrow] = bv.x;  Bs[lcol + 1][lrow] = bv.y;
        Bs[lcol + 2][lrow] = bv.z;  Bs[lcol + 3][lrow] = bv.w;
        __syncthreads();
#pragma unroll
        for (int kk = 0; kk < 16; ++kk) {
            float4 a = *reinterpret_cast<const float4*>(&As[kk][ty * 4]);
            float4 b = *reinterpret_cast<const float4*>(&Bs[kk][tx * 4]);
            acc[0][0] = fmaf(a.x, b.x, acc[0][0]); acc[0][1] = fmaf(a.x, b.y, acc[0][1]);
            acc[0][2] = fmaf(a.x, b.z, acc[0][2]); acc[0][3] = fmaf(a.x, b.w, acc[0][3]);
            acc[1][0] = fmaf(a.y, b.x, acc[1][0]); acc[1][1] = fmaf(a.y, b.y, acc[1][1]);
            acc[1][2] = fmaf(a.y, b.z, acc[1][2]); acc[1][3] = fmaf(a.y, b.w, acc[1][3]);
            acc[2][0] = fmaf(a.z, b.x, acc[2][0]); acc[2][1] = fmaf(a.z, b.y, acc[2][1]);
            acc[2][2] = fmaf(a.z, b.z, acc[2][2]); acc[2][3] = fmaf(a.z, b.w, acc[2][3]);
            acc[3][0] = fmaf(a.w, b.x, acc[3][0]); acc[3][1] = fmaf(a.w, b.y, acc[3][1]);
            acc[3][2] = fmaf(a.w, b.z, acc[3][2]); acc[3][3] = fmaf(a.w, b.w, acc[3][3]);
        }
        __syncthreads();
    }

#pragma unroll
    for (int i = 0; i < 4; ++i) {
        const size_t row = (size_t)(m0 + ty * 4 + i) * N + n0 + tx * 4;
#pragma unroll
        for (int j = 0; j < 4; ++j)
            C[row + j] = acc[i][j] + __ldg(&bias[n0 + tx * 4 + j]);
    }
}

// =====================================================================
// Head GEMM (phase 3), FFMA2: C[M][256] = A[M][512] @ B[256][512]^T + bias
// grid = (M/128, 2), block 256, 128x128 tile, BK=8, 8x8 microtile.
// =====================================================================
__global__ __launch_bounds__(256, 1)
void gemm_head_f32x2(const float* __restrict__ A,
                     const float* __restrict__ Bm,
                     const float* __restrict__ bias,
                     float* __restrict__ C)
{
    __shared__ float As[8][128];
    __shared__ float Bs[8][128];

    const int tid  = threadIdx.x;
    const int m0   = blockIdx.x * 128;
    const int n0   = blockIdx.y * 128;
    const int lrow = tid >> 1;
    const int lcol = (tid & 1) * 4;
    const int tx   = tid & 15;      // 8-col group
    const int ty   = tid >> 4;      // 8-row group

    ull acc[8][4];
#pragma unroll
    for (int i = 0; i < 8; ++i)
#pragma unroll
        for (int j = 0; j < 4; ++j) acc[i][j] = 0ull;

    for (int k0 = 0; k0 < 512; k0 += 8) {
        float4 av = *reinterpret_cast<const float4*>(A  + (size_t)(m0 + lrow) * 512 + k0 + lcol);
        float4 bv = *reinterpret_cast<const float4*>(Bm + (size_t)(n0 + lrow) * 512 + k0 + lcol);
        As[lcol + 0][lrow] = av.x;  As[lcol + 1][lrow] = av.y;
        As[lcol + 2][lrow] = av.z;  As[lcol + 3][lrow] = av.w;
        Bs[lcol + 0][lrow] = bv.x;  Bs[lcol + 1][lrow] = bv.y;
        Bs[lcol + 2][lrow] = bv.z;  Bs[lcol + 3][lrow] = bv.w;
        __syncthreads();
#pragma unroll
        for (int kk = 0; kk < 8; ++kk) {
            float4 a0 = *reinterpret_cast<const float4*>(&As[kk][ty * 8]);
            float4 a1 = *reinterpret_cast<const float4*>(&As[kk][ty * 8 + 4]);
            ulonglong2 b0 = *reinterpret_cast<const ulonglong2*>(&Bs[kk][tx * 8]);
            ulonglong2 b1 = *reinterpret_cast<const ulonglong2*>(&Bs[kk][tx * 8 + 4]);
            ull ad[8];
            ad[0] = fdup(a0.x); ad[1] = fdup(a0.y); ad[2] = fdup(a0.z); ad[3] = fdup(a0.w);
            ad[4] = fdup(a1.x); ad[5] = fdup(a1.y); ad[6] = fdup(a1.z); ad[7] = fdup(a1.w);
#pragma unroll
            for (int i = 0; i < 8; ++i) {
                acc[i][0] = ffma2(ad[i], b0.x, acc[i][0]);
                acc[i][1] = ffma2(ad[i], b0.y, acc[i][1]);
                acc[i][2] = ffma2(ad[i], b1.x, acc[i][2]);
                acc[i][3] = ffma2(ad[i], b1.y, acc[i][3]);
            }
        }
        __syncthreads();
    }

#pragma unroll
    for (int i = 0; i < 8; ++i) {
        const size_t row = (size_t)(m0 + ty * 8 + i) * 256 + n0 + tx * 8;
#pragma unroll
        for (int jp = 0; jp < 4; ++jp) {
            float2 p = unpack2(acc[i][jp]);
            C[row + jp * 2 + 0] = p.x + __ldg(&bias[n0 + tx * 8 + jp * 2 + 0]);
            C[row + jp * 2 + 1] = p.y + __ldg(&bias[n0 + tx * 8 + jp * 2 + 1]);
        }
    }
}

// =====================================================================
__global__ void reset_bar()
{
    if (threadIdx.x < 4) g_bar[threadIdx.x * 32] = 0u;
}

// =====================================================================
// Persistent recurrence. grid = 128 CTAs = 4 batch-groups x 32 out-tiles.
// block 256. smem: wsm2 64KB (W_h dup f32x2) + hsm 32KB + red 16KB = 112KB.
// FFMA2 compute, conflict-free red writes (rotated cols), 2-way reads.
// =====================================================================
__global__ __launch_bounds__(256, 1)
void rnn_scan(const int* __restrict__ x,
              const float* __restrict__ h0,
              const float* __restrict__ w_cell)
{
    extern __shared__ ull smu[];
    ull*   wsm2 = smu;                          // [e*16 + o]  dup pairs
    float* hsm  = reinterpret_cast<float*>(smu + 8192);  // [e*16 + b]
    float* red  = hsm + 8192;                   // [(s*16+g)*16 + col]

    const int tid = threadIdx.x;
    const int bt  = blockIdx.x >> 5;   // batch group 0..3
    const int ot  = blockIdx.x & 31;   // output tile 0..31
    const int b0  = bt * 16;
    const int o0  = ot * 16;

    // ---- load W_h slice once, duplicated into f32x2 pairs ----
    for (int idx = tid; idx < 16 * 512; idx += 256) {
        const int o = idx >> 9;
        const int e = idx & 511;
        wsm2[e * 16 + o] = fdup(w_cell[(size_t)(o0 + o) * 1024 + 512 + e]);
    }

    // compute mapping: s = subtile (4b x 4o), g = k-group (32 e)
    const int s  = tid & 15;
    const int g  = tid >> 4;
    const int bq = s >> 2;
    const int oq = s & 3;

    // h-stage mapping (conflict-reduced)
    const int lb = tid & 15;           // local batch row
    const int ec = (tid >> 4) * 4;     // e chunk base

    // reducer/output mapping: rs = subtile, ridx = element
    const int rs   = tid & 15;
    const int ridx = tid >> 4;
    const int my_b = b0 + (rs >> 2) * 4 + (ridx >> 2);
    const int my_o = o0 + (rs & 3) * 4 + (ridx & 3);
    const int rcol = (ridx + rs) & 15;

    const unsigned long long bar_ga =
        __cvta_generic_to_global((void*)&g_bar[bt * 32]);

    for (int t = 0; t < TT; ++t) {
        // prefetch token + input projection (independent of h)
        const int   xv = __ldg(x + (size_t)my_b * TT + t);
        const float xw = __ldg(&g_xwv[(size_t)xv * EE + my_o]);

        // ---- stage h_prev into hsm [e][16] ----
        if (t == 0) {
            for (int e = tid; e < EE; e += 256) {
                const float hv = __ldg(&h0[e]);
#pragma unroll
                for (int b = 0; b < 16; ++b) hsm[e * 16 + b] = hv;
            }
        } else {
            const float* src = g_hs + ((size_t)(b0 + lb) * TT + (t - 1)) * EE;
#pragma unroll
            for (int r = 0; r < 8; ++r) {
                const int e = ec + r * 64;
                const float4 v = __ldcg(reinterpret_cast<const float4*>(src + e));
                hsm[(e + 0) * 16 + lb] = v.x;
                hsm[(e + 1) * 16 + lb] = v.y;
                hsm[(e + 2) * 16 + lb] = v.z;
                hsm[(e + 3) * 16 + lb] = v.w;
            }
        }
        __syncthreads();

        // ---- partial GEMM: 4b x 4o x 32e per thread, FFMA2 ----
        ull acc[4][2];
#pragma unroll
        for (int o = 0; o < 4; ++o) { acc[o][0] = 0ull; acc[o][1] = 0ull; }

        const int eb = g * 32;
#pragma unroll 8
        for (int e = eb; e < eb + 32; ++e) {
            const ulonglong2 h01 = *reinterpret_cast<const ulonglong2*>(hsm + e * 16 + bq * 4);
            const ulonglong2 w01 = *reinterpret_cast<const ulonglong2*>(wsm2 + e * 16 + oq * 4);
            const ulonglong2 w23 = *reinterpret_cast<const ulonglong2*>(wsm2 + e * 16 + oq * 4 + 2);
            acc[0][0] = ffma2(h01.x, w01.x, acc[0][0]);
            acc[0][1] = ffma2(h01.y, w01.x, acc[0][1]);
            acc[1][0] = ffma2(h01.x, w01.y, acc[1][0]);
            acc[1][1] = ffma2(h01.y, w01.y, acc[1][1]);
            acc[2][0] = ffma2(h01.x, w23.x, acc[2][0]);
            acc[2][1] = ffma2(h01.y, w23.x, acc[2][1]);
            acc[3][0] = ffma2(h01.x, w23.y, acc[3][0]);
            acc[3][1] = ffma2(h01.y, w23.y, acc[3][1]);
        }

        // ---- write partials, rotated col => conflict-free ----
        {
            float* rr = red + (s * 16 + g) * 16;
#pragma unroll
            for (int o = 0; o < 4; ++o) {
#pragma unroll
                for (int bp = 0; bp < 2; ++bp) {
                    const float2 p = unpack2(acc[o][bp]);
                    const int i0 = (2 * bp) * 4 + o;        // b_local even
                    const int i1 = (2 * bp + 1) * 4 + o;    // b_local odd
                    rr[(i0 + s) & 15] = p.x;
                    rr[(i1 + s) & 15] = p.y;
                }
            }
        }
        __syncthreads();

        // ---- reduce 16 k-groups, tanh, store h_t (through L2) ----
        {
            float sum = 0.0f;
#pragma unroll
            for (int gg = 0; gg < 16; ++gg)
                sum += red[(rs * 16 + gg) * 16 + rcol];
            const float hval = tanhf(sum + xw);
            __stcg(&g_hs[((size_t)my_b * TT + t) * EE + my_o], hval);
        }

        // ---- per-group barrier: release-add / acquire-spin ----
        if (t < TT - 1) {
            __syncthreads();
            if (tid == 0) {
                const unsigned int target = 32u * (unsigned int)(t + 1);
                unsigned int prev;
                asm volatile("atom.add.release.gpu.global.u32 %0, [%1], %2;"
                             : "=r"(prev) : "l"(bar_ga), "r"(1u) : "memory");
                if (prev + 1u < target) {
                    unsigned int cur;
                    do {
                        asm volatile("ld.acquire.gpu.global.u32 %0, [%1];"
                                     : "=r"(cur) : "l"(bar_ga) : "memory");
                    } while (cur < target);
                }
            }
            __syncthreads();
        }
    }
}

// =====================================================================
// host-side launch
// inputs: 0=x 1=emb 2=w_cell 3=b_cell 4=w_head 5=b_head 6=h0
// =====================================================================
extern "C" void kernel_launch(void* const* d_in, const int* in_sizes, int n_in,
                              void* d_out, int out_size)
{
    const int*   x      = (const int*)  d_in[0];
    const float* emb    = (const float*)d_in[1];
    const float* w_cell = (const float*)d_in[2];
    const float* b_cell = (const float*)d_in[3];
    const float* w_head = (const float*)d_in[4];
    const float* b_head = (const float*)d_in[5];
    const float* h0     = (const float*)d_in[6];
    float*       out    = (float*)d_out;

    void* p_xwv = nullptr;
    void* p_hs  = nullptr;
    cudaGetSymbolAddress(&p_xwv, g_xwv);
    cudaGetSymbolAddress(&p_hs,  g_hs);

    // Phase 1: XWV = emb @ w_x^T + b_cell   (256 x 512, K=512)
    {
        dim3 grid(VV / 64, EE / 64);
        gemm_atb<<<grid, 256>>>(emb, EE, w_cell, 2 * EE, b_cell,
                                (float*)p_xwv, EE, EE);
    }

    // Phase 2: recurrence
    reset_bar<<<1, 32>>>();
    cudaFuncSetAttribute(rnn_scan,
                         cudaFuncAttributeMaxDynamicSharedMemorySize, 114688);
    rnn_scan<<<128, 256, 114688>>>(x, h0, w_cell);

    // Phase 3: head GEMM  out = hs @ w_head^T + b_head
    {
        dim3 grid((BB * TT) / 128, VV / 128);
        gemm_head_f32x2<<<grid, 256>>>((const float*)p_hs, w_head, b_head, out);
    }
}

// round 6
// speedup vs baseline: 1.8426x; 1.8426x over previous
#include <cuda_runtime.h>
#include <cstdint>

#define BB 64      // batch
#define TT 1024    // time steps
#define EE 512     // embedding
#define VV 256     // vocab

typedef unsigned long long ull;

// ---------------- device scratch ----------------
__device__ float g_xwv[VV * EE];                 // XWV[v][o] = emb[v]·w_x[o] + b_cell[o]
__device__ float g_hs[(size_t)BB * TT * EE];     // h_t, layout [b][t][e]  (128 MB)
__device__ unsigned int g_bar[4 * 32];           // per-group counter, 128B apart

// ---------------- f32x2 helpers ----------------
__device__ __forceinline__ ull ffma2(ull a, ull b, ull c) {
    ull d;
    asm("fma.rn.f32x2 %0, %1, %2, %3;" : "=l"(d) : "l"(a), "l"(b), "l"(c));
    return d;
}
__device__ __forceinline__ ull fdup(float s) {
    ull d;
    asm("mov.b64 %0, {%1, %1};" : "=l"(d) : "f"(s));
    return d;
}
__device__ __forceinline__ float2 unpack2(ull v) {
    float2 r;
    asm("mov.b64 {%0, %1}, %2;" : "=f"(r.x), "=f"(r.y) : "l"(v));
    return r;
}

// =====================================================================
// Phase-1 GEMM (tiny):  C[M][N] = A[M][K] @ B[N][K]^T + bias[N]
// =====================================================================
__global__ void gemm_atb(const float* __restrict__ A, int lda,
                         const float* __restrict__ Bm, int ldb,
                         const float* __restrict__ bias,
                         float* __restrict__ C, int N, int K)
{
    __shared__ float As[16][64];
    __shared__ float Bs[16][64];

    const int tid  = threadIdx.x;
    const int m0   = blockIdx.x * 64;
    const int n0   = blockIdx.y * 64;
    const int tx   = tid & 15;
    const int ty   = tid >> 4;
    const int lrow = tid >> 2;
    const int lcol = (tid & 3) * 4;

    float acc[4][4];
#pragma unroll
    for (int i = 0; i < 4; ++i)
#pragma unroll
        for (int j = 0; j < 4; ++j) acc[i][j] = 0.0f;

    for (int k0 = 0; k0 < K; k0 += 16) {
        float4 av = *reinterpret_cast<const float4*>(A  + (size_t)(m0 + lrow) * lda + k0 + lcol);
        float4 bv = *reinterpret_cast<const float4*>(Bm + (size_t)(n0 + lrow) * ldb + k0 + lcol);
        As[lcol + 0][lrow] = av.x;  As[lcol + 1][lrow] = av.y;
        As[lcol + 2][lrow] = av.z;  As[lcol + 3][lrow] = av.w;
        Bs[lcol + 0][lrow] = bv.x;  Bs[lcol + 1][lrow] = bv.y;
        Bs[lcol + 2][lrow] = bv.z;  Bs[lcol + 3][lrow] = bv.w;
        __syncthreads();
#pragma unroll
        for (int kk = 0; kk < 16; ++kk) {
            float4 a = *reinterpret_cast<const float4*>(&As[kk][ty * 4]);
            float4 b = *reinterpret_cast<const float4*>(&Bs[kk][tx * 4]);
            acc[0][0] = fmaf(a.x, b.x, acc[0][0]); acc[0][1] = fmaf(a.x, b.y, acc[0][1]);
            acc[0][2] = fmaf(a.x, b.z, acc[0][2]); acc[0][3] = fmaf(a.x, b.w, acc[0][3]);
            acc[1][0] = fmaf(a.y, b.x, acc[1][0]); acc[1][1] = fmaf(a.y, b.y, acc[1][1]);
            acc[1][2] = fmaf(a.y, b.z, acc[1][2]); acc[1][3] = fmaf(a.y, b.w, acc[1][3]);
            acc[2][0] = fmaf(a.z, b.x, acc[2][0]); acc[2][1] = fmaf(a.z, b.y, acc[2][1]);
            acc[2][2] = fmaf(a.z, b.z, acc[2][2]); acc[2][3] = fmaf(a.z, b.w, acc[2][3]);
            acc[3][0] = fmaf(a.w, b.x, acc[3][0]); acc[3][1] = fmaf(a.w, b.y, acc[3][1]);
            acc[3][2] = fmaf(a.w, b.z, acc[3][2]); acc[3][3] = fmaf(a.w, b.w, acc[3][3]);
        }
        __syncthreads();
    }

#pragma unroll
    for (int i = 0; i < 4; ++i) {
        const size_t row = (size_t)(m0 + ty * 4 + i) * N + n0 + tx * 4;
#pragma unroll
        for (int j = 0; j < 4; ++j)
            C[row + j] = acc[i][j] + __ldg(&bias[n0 + tx * 4 + j]);
    }
}

// =====================================================================
// Head GEMM: C[M][256] = A[M][512] @ B[256][512]^T + bias
// 64x128 tile, BK=16, microtile 4m x 8n (f32x2), 2 CTAs/SM.
// =====================================================================
__global__ __launch_bounds__(256, 2)
void gemm_head_f32x2(const float* __restrict__ A,
                     const float* __restrict__ Bm,
                     const float* __restrict__ bias,
                     float* __restrict__ C)
{
    __shared__ float As[16][68];
    __shared__ float Bs[16][136];

    const int tid  = threadIdx.x;
    const int m0   = blockIdx.x * 64;
    const int n0   = blockIdx.y * 128;
    const int arow = tid >> 2;          // 0..63
    const int acol = (tid & 3) * 4;
    const int brow = tid >> 1;          // 0..127
    const int bcol = (tid & 1) * 4;
    const int tx   = tid & 15;          // n group: 8 outs
    const int ty   = tid >> 4;          // m group: 4 rows

    ull acc[4][4];
#pragma unroll
    for (int i = 0; i < 4; ++i)
#pragma unroll
        for (int j = 0; j < 4; ++j) acc[i][j] = 0ull;

    for (int k0 = 0; k0 < 512; k0 += 16) {
        {
            float4 av = *reinterpret_cast<const float4*>(A + (size_t)(m0 + arow) * 512 + k0 + acol);
            As[acol + 0][arow] = av.x;  As[acol + 1][arow] = av.y;
            As[acol + 2][arow] = av.z;  As[acol + 3][arow] = av.w;
            float4 b0 = *reinterpret_cast<const float4*>(Bm + (size_t)(n0 + brow) * 512 + k0 + bcol);
            float4 b1 = *reinterpret_cast<const float4*>(Bm + (size_t)(n0 + brow) * 512 + k0 + bcol + 8);
            Bs[bcol + 0][brow] = b0.x;  Bs[bcol + 1][brow] = b0.y;
            Bs[bcol + 2][brow] = b0.z;  Bs[bcol + 3][brow] = b0.w;
            Bs[bcol + 8][brow] = b1.x;  Bs[bcol + 9][brow] = b1.y;
            Bs[bcol + 10][brow] = b1.z; Bs[bcol + 11][brow] = b1.w;
        }
        __syncthreads();
#pragma unroll
        for (int kk = 0; kk < 16; ++kk) {
            const float4 a = *reinterpret_cast<const float4*>(&As[kk][ty * 4]);
            const ulonglong2 bA = *reinterpret_cast<const ulonglong2*>(&Bs[kk][tx * 8]);
            const ulonglong2 bB = *reinterpret_cast<const ulonglong2*>(&Bs[kk][tx * 8 + 4]);
            ull ad0 = fdup(a.x), ad1 = fdup(a.y), ad2 = fdup(a.z), ad3 = fdup(a.w);
            acc[0][0] = ffma2(ad0, bA.x, acc[0][0]); acc[0][1] = ffma2(ad0, bA.y, acc[0][1]);
            acc[0][2] = ffma2(ad0, bB.x, acc[0][2]); acc[0][3] = ffma2(ad0, bB.y, acc[0][3]);
            acc[1][0] = ffma2(ad1, bA.x, acc[1][0]); acc[1][1] = ffma2(ad1, bA.y, acc[1][1]);
            acc[1][2] = ffma2(ad1, bB.x, acc[1][2]); acc[1][3] = ffma2(ad1, bB.y, acc[1][3]);
            acc[2][0] = ffma2(ad2, bA.x, acc[2][0]); acc[2][1] = ffma2(ad2, bA.y, acc[2][1]);
            acc[2][2] = ffma2(ad2, bB.x, acc[2][2]); acc[2][3] = ffma2(ad2, bB.y, acc[2][3]);
            acc[3][0] = ffma2(ad3, bA.x, acc[3][0]); acc[3][1] = ffma2(ad3, bA.y, acc[3][1]);
            acc[3][2] = ffma2(ad3, bB.x, acc[3][2]); acc[3][3] = ffma2(ad3, bB.y, acc[3][3]);
        }
        __syncthreads();
    }

    const float4 bi0 = *reinterpret_cast<const float4*>(bias + n0 + tx * 8);
    const float4 bi1 = *reinterpret_cast<const float4*>(bias + n0 + tx * 8 + 4);
#pragma unroll
    for (int i = 0; i < 4; ++i) {
        float* crow = C + (size_t)(m0 + ty * 4 + i) * 256 + n0 + tx * 8;
        const float2 p0 = unpack2(acc[i][0]);
        const float2 p1 = unpack2(acc[i][1]);
        const float2 p2 = unpack2(acc[i][2]);
        const float2 p3 = unpack2(acc[i][3]);
        float4 o0 = make_float4(p0.x + bi0.x, p0.y + bi0.y, p1.x + bi0.z, p1.y + bi0.w);
        float4 o1 = make_float4(p2.x + bi1.x, p2.y + bi1.y, p3.x + bi1.z, p3.y + bi1.w);
        *reinterpret_cast<float4*>(crow)     = o0;
        *reinterpret_cast<float4*>(crow + 4) = o1;
    }
}

// =====================================================================
__global__ void reset_bar()
{
    if (threadIdx.x < 4) g_bar[threadIdx.x * 32] = 0u;
}

// =====================================================================
// Persistent recurrence. grid = 128 = 4 batch-groups x 32 out-tiles.
// Thread (eg, o): W_h[o][eg*32 .. +32) resident in 16 f32x2 REGISTERS.
// Per step: stage h[16b][512e] -> smem [b][e] (pad 576, eg-chunk stride 36),
// each thread computes 16 batch-partials (h broadcast across o-lanes),
// smem reduce over 16 eg, tanh, STCG, release/acquire group barrier.
// smem = 16*576*4 + 4096*4 = 53248 B.
// =====================================================================
#define HP  576    // padded floats per batch row
#define EGS 36     // floats per eg chunk (32 data + 4 pad)

__global__ __launch_bounds__(256, 1)
void rnn_scan(const int* __restrict__ x,
              const float* __restrict__ h0,
              const float* __restrict__ w_cell)
{
    extern __shared__ float sm[];
    float* hsm = sm;              // [b*HP + (e>>5)*EGS + (e&31)]
    float* red = sm + 16 * HP;    // [b*256 + eg*16 + o]

    const int tid = threadIdx.x;
    const int bt  = blockIdx.x >> 5;
    const int ot  = blockIdx.x & 31;
    const int b0  = bt * 16;
    const int o0  = ot * 16;

    const int eg = tid >> 4;      // k-group: 32 e
    const int o  = tid & 15;      // output within tile

    // ---- W_h slice into registers, as f32x2 pairs (once for all steps) ----
    ull w2[16];
    {
        const float* wrow = w_cell + (size_t)(o0 + o) * 1024 + 512 + eg * 32;
#pragma unroll
        for (int p = 0; p < 16; ++p)
            w2[p] = *reinterpret_cast<const ull*>(wrow + 2 * p);
    }

    // staging mapping
    const int lb = tid >> 4;           // batch row 0..15
    const int c  = tid & 15;           // 16 loaders per row

    // reducer/output mapping
    const int rb = tid >> 4;
    const int ro = tid & 15;

    const unsigned long long bar_ga =
        __cvta_generic_to_global((void*)&g_bar[bt * 32]);

    for (int t = 0; t < TT; ++t) {
        // prefetch token + input projection (independent of h)
        const int   xv = __ldg(x + (size_t)(b0 + rb) * TT + t);
        const float xw = __ldg(&g_xwv[(size_t)xv * EE + o0 + ro]);

        // ---- stage h_prev into hsm ----
        if (t == 0) {
            for (int e = tid; e < EE; e += 256) {
                const float hv = __ldg(&h0[e]);
                const int off = (e >> 5) * EGS + (e & 31);
#pragma unroll
                for (int b = 0; b < 16; ++b) hsm[b * HP + off] = hv;
            }
        } else {
            const float* src = g_hs + ((size_t)(b0 + lb) * TT + (t - 1)) * EE;
            float* dstrow = hsm + lb * HP;
#pragma unroll
            for (int r = 0; r < 8; ++r) {
                const int e = r * 64 + c * 4;
                const float4 v = __ldcg(reinterpret_cast<const float4*>(src + e));
                *reinterpret_cast<float4*>(dstrow + (e >> 5) * EGS + (e & 31)) = v;
            }
        }
        __syncthreads();

        // ---- per-thread: 16 batch dot-partials over this thread's 32 e ----
#pragma unroll 4
        for (int b = 0; b < 16; ++b) {
            const float* hb = hsm + b * HP + eg * EGS;
            ull a0 = 0ull, a1 = 0ull;
#pragma unroll
            for (int j = 0; j < 8; ++j) {
                const ulonglong2 hv = *reinterpret_cast<const ulonglong2*>(hb + j * 4);
                a0 = ffma2(hv.x, w2[2 * j + 0], a0);
                a1 = ffma2(hv.y, w2[2 * j + 1], a1);
            }
            const float2 s0 = unpack2(a0);
            const float2 s1 = unpack2(a1);
            red[b * 256 + eg * 16 + o] = (s0.x + s1.x) + (s0.y + s1.y);
        }
        __syncthreads();

        // ---- reduce 16 eg partials, tanh, store h_t through L2 ----
        {
            float sum = 0.0f;
#pragma unroll
            for (int gg = 0; gg < 16; ++gg)
                sum += red[rb * 256 + gg * 16 + ro];
            const float hval = tanhf(sum + xw);
            __stcg(&g_hs[((size_t)(b0 + rb) * TT + t) * EE + o0 + ro], hval);
        }

        // ---- per-group barrier: release-add / acquire-spin ----
        if (t < TT - 1) {
            __syncthreads();
            if (tid == 0) {
                const unsigned int target = 32u * (unsigned int)(t + 1);
                unsigned int prev;
                asm volatile("atom.add.release.gpu.global.u32 %0, [%1], %2;"
                             : "=r"(prev) : "l"(bar_ga), "r"(1u) : "memory");
                if (prev + 1u < target) {
                    unsigned int cur;
                    do {
                        asm volatile("ld.acquire.gpu.global.u32 %0, [%1];"
                                     : "=r"(cur) : "l"(bar_ga) : "memory");
                    } while (cur < target);
                }
            }
            __syncthreads();
        }
    }
}

// =====================================================================
// host-side launch
// inputs: 0=x 1=emb 2=w_cell 3=b_cell 4=w_head 5=b_head 6=h0
// =====================================================================
extern "C" void kernel_launch(void* const* d_in, const int* in_sizes, int n_in,
                              void* d_out, int out_size)
{
    const int*   x      = (const int*)  d_in[0];
    const float* emb    = (const float*)d_in[1];
    const float* w_cell = (const float*)d_in[2];
    const float* b_cell = (const float*)d_in[3];
    const float* w_head = (const float*)d_in[4];
    const float* b_head = (const float*)d_in[5];
    const float* h0     = (const float*)d_in[6];
    float*       out    = (float*)d_out;

    void* p_xwv = nullptr;
    void* p_hs  = nullptr;
    cudaGetSymbolAddress(&p_xwv, g_xwv);
    cudaGetSymbolAddress(&p_hs,  g_hs);

    // Phase 1: XWV = emb @ w_x^T + b_cell   (256 x 512, K=512)
    {
        dim3 grid(VV / 64, EE / 64);
        gemm_atb<<<grid, 256>>>(emb, EE, w_cell, 2 * EE, b_cell,
                                (float*)p_xwv, EE, EE);
    }

    // Phase 2: recurrence
    reset_bar<<<1, 32>>>();
    cudaFuncSetAttribute(rnn_scan,
                         cudaFuncAttributeMaxDynamicSharedMemorySize, 55296);
    rnn_scan<<<128, 256, 55296>>>(x, h0, w_cell);

    // Phase 3: head GEMM  out = hs @ w_head^T + b_head
    {
        dim3 grid((BB * TT) / 64, VV / 128);
        gemm_head_f32x2<<<grid, 256>>>((const float*)p_hs, w_head, b_head, out);
    }
}